// round 1
// baseline (speedup 1.0000x reference)
#include <cuda_runtime.h>
#include <cuda_bf16.h>
#include <math.h>

// Problem constants
#define BB 2
#define SS 2048
#define DIM 4096
#define NH 32
#define NKV 8
#define HD 128
#define MROWS (BB*SS)          // 4096
#define SOFT_SCALE 0.08838834764831845f  // 1/sqrt(128)

// Scratch (allocation-free rule: __device__ globals)
__device__ float g_q[(size_t)MROWS * NH * HD];     // 64 MB
__device__ float g_k[(size_t)MROWS * NKV * HD];    // 16 MB
__device__ float g_v[(size_t)MROWS * NKV * HD];    // 16 MB
__device__ float g_attn[(size_t)MROWS * NH * HD];  // 64 MB

// ---------------------------------------------------------------------------
// SGEMM: C[M,N] = A[M,K] @ B[K,N], fp32, BM=BN=128, BK=16, 256 thr, 8x8/thr
// M,N multiples of 128; K multiple of 16.
// ---------------------------------------------------------------------------
__global__ __launch_bounds__(256) void sgemm_kernel(
    const float* __restrict__ A, const float* __restrict__ B,
    float* __restrict__ C, int M, int N, int K)
{
    constexpr int BM = 128, BN = 128, BK = 16;
    __shared__ float As[BK][BM];   // transposed A tile
    __shared__ float Bs[BK][BN];

    const int t  = threadIdx.x;
    const int bm = blockIdx.y * BM;
    const int bn = blockIdx.x * BN;
    const int ty = t >> 4;          // 0..15
    const int tx = t & 15;          // 0..15

    const int aRow = t >> 2;        // 0..63
    const int aCol = (t & 3) * 4;   // 0,4,8,12
    const int bRow = t >> 5;        // 0..7
    const int bCol = (t & 31) * 4;  // 0..124

    const float* Aptr = A + (size_t)(bm + aRow) * K + aCol;
    const float* Bptr = B + (size_t)bRow * N + bn + bCol;

    float acc[8][8];
    #pragma unroll
    for (int i = 0; i < 8; i++)
        #pragma unroll
        for (int j = 0; j < 8; j++) acc[i][j] = 0.f;

    for (int k0 = 0; k0 < K; k0 += BK) {
        float4 a0 = *(const float4*)(Aptr + k0);
        float4 a1 = *(const float4*)(Aptr + (size_t)64 * K + k0);
        float4 b0 = *(const float4*)(Bptr + (size_t)k0 * N);
        float4 b1 = *(const float4*)(Bptr + (size_t)(k0 + 8) * N);

        As[aCol + 0][aRow] = a0.x;
        As[aCol + 1][aRow] = a0.y;
        As[aCol + 2][aRow] = a0.z;
        As[aCol + 3][aRow] = a0.w;
        As[aCol + 0][aRow + 64] = a1.x;
        As[aCol + 1][aRow + 64] = a1.y;
        As[aCol + 2][aRow + 64] = a1.z;
        As[aCol + 3][aRow + 64] = a1.w;
        *(float4*)&Bs[bRow][bCol]     = b0;
        *(float4*)&Bs[bRow + 8][bCol] = b1;
        __syncthreads();

        #pragma unroll
        for (int kk = 0; kk < BK; kk++) {
            float4 ra0 = *(const float4*)&As[kk][ty * 8];
            float4 ra1 = *(const float4*)&As[kk][ty * 8 + 4];
            float4 rb0 = *(const float4*)&Bs[kk][tx * 8];
            float4 rb1 = *(const float4*)&Bs[kk][tx * 8 + 4];
            float a[8] = {ra0.x, ra0.y, ra0.z, ra0.w, ra1.x, ra1.y, ra1.z, ra1.w};
            float b[8] = {rb0.x, rb0.y, rb0.z, rb0.w, rb1.x, rb1.y, rb1.z, rb1.w};
            #pragma unroll
            for (int i = 0; i < 8; i++)
                #pragma unroll
                for (int j = 0; j < 8; j++)
                    acc[i][j] = fmaf(a[i], b[j], acc[i][j]);
        }
        __syncthreads();
    }

    #pragma unroll
    for (int i = 0; i < 8; i++) {
        float* Crow = C + (size_t)(bm + ty * 8 + i) * N + bn + tx * 8;
        float4 c0 = {acc[i][0], acc[i][1], acc[i][2], acc[i][3]};
        float4 c1 = {acc[i][4], acc[i][5], acc[i][6], acc[i][7]};
        *(float4*)(Crow)     = c0;
        *(float4*)(Crow + 4) = c1;
    }
}

// ---------------------------------------------------------------------------
// RoPE (interleaved pairs): x layout [B*S, nheads*128]
// ---------------------------------------------------------------------------
__global__ void rope_kernel(float* __restrict__ x,
                            const float* __restrict__ cosT,
                            const float* __restrict__ sinT,
                            const int* __restrict__ start_pos,
                            int nheads)
{
    int idx = blockIdx.x * blockDim.x + threadIdx.x;
    int total = BB * SS * nheads * (HD / 2);
    if (idx >= total) return;
    int p = idx & 63;                    // pair index 0..63
    int h = (idx >> 6) % nheads;
    int srow = (idx / (64 * nheads)) % SS;
    int b = idx / (64 * nheads * SS);
    int pos = start_pos[0] + srow;
    float c = cosT[pos * 64 + p];
    float s = sinT[pos * 64 + p];
    size_t base = ((size_t)(b * SS + srow) * nheads + h) * HD + 2 * p;
    float xr = x[base];
    float xi = x[base + 1];
    x[base]     = xr * c - xi * s;
    x[base + 1] = xr * s + xi * c;
}

// ---------------------------------------------------------------------------
// Attention: one CTA per (qtile of 64, q-head, batch). Online softmax over
// 32 key tiles of 64. 256 threads: 4 threads per q-row; each thread owns
// 32 of 128 output dims (float4 groups i*4+sub for i=0..7).
// Padded smem strides (132 / 68 floats) for conflict-free LDS.
// ---------------------------------------------------------------------------
#define QSTR 132
#define PSTR 68
#define ATTN_SMEM ((64*QSTR*3 + 64*PSTR) * 4)   // 118784 bytes

__global__ __launch_bounds__(256) void attn_kernel(
    const float* __restrict__ q, const float* __restrict__ k,
    const float* __restrict__ v, float* __restrict__ out)
{
    extern __shared__ float sm[];
    float* sQ = sm;                 // 64 x 132
    float* sK = sQ + 64 * QSTR;     // 64 x 132
    float* sV = sK + 64 * QSTR;     // 64 x 132
    float* sP = sV + 64 * QSTR;     // 64 x 68

    const int tid = threadIdx.x;
    const int row = tid >> 2;       // q row within tile (0..63)
    const int sub = tid & 3;        // 0..3

    const int qt = blockIdx.x;      // 0..31
    const int hq = blockIdx.y;      // 0..31
    const int b  = blockIdx.z;      // 0..1
    const int hk = hq >> 2;

    const float* qbase = q + ((size_t)(b * SS + qt * 64)) * (NH * HD) + hq * HD;
    const float* kbase = k + ((size_t)(b * SS)) * (NKV * HD) + hk * HD;
    const float* vbase = v + ((size_t)(b * SS)) * (NKV * HD) + hk * HD;

    // load Q tile (64x128)
    #pragma unroll
    for (int i = 0; i < 8; i++) {
        int idx = tid + i * 256;        // 0..2047
        int r = idx >> 5;
        int c4 = idx & 31;
        float4 val = *(const float4*)(qbase + (size_t)r * (NH * HD) + c4 * 4);
        *(float4*)(sQ + r * QSTR + c4 * 4) = val;
    }

    float o[32];
    #pragma unroll
    for (int i = 0; i < 32; i++) o[i] = 0.f;
    float m = -3.0e38f;
    float l = 0.f;

    for (int kt = 0; kt < SS / 64; kt++) {
        // load K,V tiles
        #pragma unroll
        for (int i = 0; i < 8; i++) {
            int idx = tid + i * 256;
            int r = idx >> 5;
            int c4 = idx & 31;
            size_t goff = (size_t)(kt * 64 + r) * (NKV * HD) + c4 * 4;
            *(float4*)(sK + r * QSTR + c4 * 4) = *(const float4*)(kbase + goff);
            *(float4*)(sV + r * QSTR + c4 * 4) = *(const float4*)(vbase + goff);
        }
        __syncthreads();

        // scores: this thread's keys are ki = sub + 4*j, j=0..15
        float s[16];
        #pragma unroll
        for (int j = 0; j < 16; j++) s[j] = 0.f;
        const float4* q4p = (const float4*)(sQ + row * QSTR);
        for (int c4 = 0; c4 < 32; c4++) {
            float4 q4 = q4p[c4];
            #pragma unroll
            for (int j = 0; j < 16; j++) {
                int ki = sub + 4 * j;
                float4 k4 = *(const float4*)(sK + ki * QSTR + c4 * 4);
                s[j] = fmaf(q4.x, k4.x, s[j]);
                s[j] = fmaf(q4.y, k4.y, s[j]);
                s[j] = fmaf(q4.z, k4.z, s[j]);
                s[j] = fmaf(q4.w, k4.w, s[j]);
            }
        }

        // online softmax (group of 4 threads = one row; same warp)
        float tmax = -3.0e38f;
        #pragma unroll
        for (int j = 0; j < 16; j++) {
            s[j] *= SOFT_SCALE;
            tmax = fmaxf(tmax, s[j]);
        }
        tmax = fmaxf(tmax, __shfl_xor_sync(0xffffffffu, tmax, 1));
        tmax = fmaxf(tmax, __shfl_xor_sync(0xffffffffu, tmax, 2));
        float nm = fmaxf(m, tmax);
        float corr = __expf(m - nm);
        float lsum = 0.f;
        #pragma unroll
        for (int j = 0; j < 16; j++) {
            float p = __expf(s[j] - nm);
            lsum += p;
            sP[row * PSTR + sub + 4 * j] = p;
        }
        lsum += __shfl_xor_sync(0xffffffffu, lsum, 1);
        lsum += __shfl_xor_sync(0xffffffffu, lsum, 2);
        l = l * corr + lsum;
        m = nm;
        #pragma unroll
        for (int i = 0; i < 32; i++) o[i] *= corr;
        __syncwarp();   // P producers/consumers per row are in the same warp

        // PV: accumulate this thread's 32 dims over 64 keys
        for (int kk = 0; kk < 64; kk++) {
            float p = sP[row * PSTR + kk];
            const float* vrow = sV + kk * QSTR;
            #pragma unroll
            for (int i = 0; i < 8; i++) {
                float4 v4 = *(const float4*)(vrow + (i * 4 + sub) * 4);
                o[i * 4 + 0] = fmaf(p, v4.x, o[i * 4 + 0]);
                o[i * 4 + 1] = fmaf(p, v4.y, o[i * 4 + 1]);
                o[i * 4 + 2] = fmaf(p, v4.z, o[i * 4 + 2]);
                o[i * 4 + 3] = fmaf(p, v4.w, o[i * 4 + 3]);
            }
        }
        __syncthreads();   // before overwriting sK/sV
    }

    // epilogue
    float inv = 1.f / l;
    size_t orow = ((size_t)(b * SS + qt * 64 + row)) * (NH * HD) + hq * HD;
    #pragma unroll
    for (int i = 0; i < 8; i++) {
        float4 val = {o[i*4+0] * inv, o[i*4+1] * inv, o[i*4+2] * inv, o[i*4+3] * inv};
        *(float4*)(out + orow + (i * 4 + sub) * 4) = val;
    }
}

// ---------------------------------------------------------------------------
extern "C" void kernel_launch(void* const* d_in, const int* in_sizes, int n_in,
                              void* d_out, int out_size)
{
    const float* x         = (const float*)d_in[0];
    const int*   start_pos = (const int*)d_in[1];
    const float* cosT      = (const float*)d_in[2];
    const float* sinT      = (const float*)d_in[3];
    const float* wq        = (const float*)d_in[4];
    const float* wk        = (const float*)d_in[5];
    const float* wv        = (const float*)d_in[6];
    const float* wo        = (const float*)d_in[7];
    float* out = (float*)d_out;

    float *q, *k, *v, *attn;
    cudaGetSymbolAddress((void**)&q,    g_q);
    cudaGetSymbolAddress((void**)&k,    g_k);
    cudaGetSymbolAddress((void**)&v,    g_v);
    cudaGetSymbolAddress((void**)&attn, g_attn);

    // QKV projections
    sgemm_kernel<<<dim3(DIM/128, MROWS/128), 256>>>(x, wq, q,    MROWS, NH  * HD, DIM);
    sgemm_kernel<<<dim3(NKV*HD/128, MROWS/128), 256>>>(x, wk, k, MROWS, NKV * HD, DIM);
    sgemm_kernel<<<dim3(NKV*HD/128, MROWS/128), 256>>>(x, wv, v, MROWS, NKV * HD, DIM);

    // RoPE
    {
        int totq = BB * SS * NH  * (HD / 2);
        int totk = BB * SS * NKV * (HD / 2);
        rope_kernel<<<(totq + 255) / 256, 256>>>(q, cosT, sinT, start_pos, NH);
        rope_kernel<<<(totk + 255) / 256, 256>>>(k, cosT, sinT, start_pos, NKV);
    }

    // attention
    cudaFuncSetAttribute(attn_kernel, cudaFuncAttributeMaxDynamicSharedMemorySize, ATTN_SMEM);
    attn_kernel<<<dim3(SS/64, NH, BB), 256, ATTN_SMEM>>>(q, k, v, attn);

    // output projection
    sgemm_kernel<<<dim3(DIM/128, MROWS/128), 256>>>(attn, wo, out, MROWS, DIM, DIM);
}

// round 6
// speedup vs baseline: 1.4525x; 1.4525x over previous
#include <cuda_runtime.h>
#include <cuda_bf16.h>
#include <cstdint>
#include <math.h>

// Problem constants
#define BB 2
#define SS 2048
#define DIM 4096
#define NH 32
#define NKV 8
#define HD 128
#define MROWS (BB*SS)          // 4096
#define SOFT_SCALE 0.08838834764831845f  // 1/sqrt(128)

// Scratch (allocation-free rule: __device__ globals)
__device__ float g_q[(size_t)MROWS * NH * HD];     // 64 MB
__device__ float g_k[(size_t)MROWS * NKV * HD];    // 16 MB
__device__ float g_v[(size_t)MROWS * NKV * HD];    // 16 MB
__device__ float g_attn[(size_t)MROWS * NH * HD];  // 64 MB

__device__ __forceinline__ float to_tf32(float x) {
    float y;
    asm("cvt.rna.tf32.f32 %0, %1;" : "=f"(y) : "f"(x));
    return y;
}

// m16n8k8 tf32 mma (legacy path — valid on base sm_103 target)
#define MMA8(d, a, b) \
    asm volatile("mma.sync.aligned.m16n8k8.row.col.f32.tf32.tf32.f32 " \
        "{%0,%1,%2,%3}, {%4,%5,%6,%7}, {%8,%9}, {%0,%1,%2,%3};" \
        : "+f"((d)[0]), "+f"((d)[1]), "+f"((d)[2]), "+f"((d)[3]) \
        : "r"((a)[0]), "r"((a)[1]), "r"((a)[2]), "r"((a)[3]), \
          "r"((b)[0]), "r"((b)[1]))

// ---------------------------------------------------------------------------
// tf32 mma.sync GEMM: C[M,N] = A[M,K] @ B[K,N]  (both row-major)
// BM=BN=128, BK=32, 256 threads (8 warps, each 32x64).
// Double-buffered smem, register-staged global loads, 1 syncthreads/iter.
// A smem stride 36 floats, B stride 136 floats: both conflict-free for the
// m16n8k8 fragment access pattern.
// ---------------------------------------------------------------------------
#define AST 36
#define BST 136
#define SA_SZ (128 * AST)     // floats per stage
#define SB_SZ (32 * BST)
#define GEMM_SMEM ((2 * (SA_SZ + SB_SZ)) * 4)   // 71680 bytes

__device__ __forceinline__ void g2r_tile(const float* __restrict__ A,
                                         const float* __restrict__ B,
                                         int m0, int n0, int k0, int K, int N,
                                         int t, float4* ra, float4* rb)
{
    #pragma unroll
    for (int i = 0; i < 4; i++) {           // A: 128 x 32
        int idx = i * 256 + t;
        int r = idx >> 3, c = idx & 7;
        ra[i] = *(const float4*)(A + (size_t)(m0 + r) * K + k0 + c * 4);
    }
    #pragma unroll
    for (int i = 0; i < 4; i++) {           // B: 32 x 128
        int idx = i * 256 + t;
        int r = idx >> 5, c = idx & 31;
        rb[i] = *(const float4*)(B + (size_t)(k0 + r) * N + n0 + c * 4);
    }
}

__device__ __forceinline__ void r2s_tile(float* sA, float* sB, int t,
                                         const float4* ra, const float4* rb)
{
    #pragma unroll
    for (int i = 0; i < 4; i++) {
        int idx = i * 256 + t;
        int r = idx >> 3, c = idx & 7;
        float4 v = ra[i];
        v.x = to_tf32(v.x); v.y = to_tf32(v.y); v.z = to_tf32(v.z); v.w = to_tf32(v.w);
        *(float4*)(sA + r * AST + c * 4) = v;
    }
    #pragma unroll
    for (int i = 0; i < 4; i++) {
        int idx = i * 256 + t;
        int r = idx >> 5, c = idx & 31;
        float4 v = rb[i];
        v.x = to_tf32(v.x); v.y = to_tf32(v.y); v.z = to_tf32(v.z); v.w = to_tf32(v.w);
        *(float4*)(sB + r * BST + c * 4) = v;
    }
}

__global__ __launch_bounds__(256) void mma_gemm(const float* __restrict__ A,
                                                const float* __restrict__ B,
                                                float* __restrict__ C,
                                                int M, int N, int K)
{
    extern __shared__ float sm[];
    float* sA = sm;                 // [2][SA_SZ]
    float* sB = sm + 2 * SA_SZ;     // [2][SB_SZ]

    const int t    = threadIdx.x;
    const int wid  = t >> 5;
    const int lane = t & 31;
    const int wm   = wid >> 1;      // 0..3  (rows wm*32)
    const int wn   = wid & 1;       // 0..1  (cols wn*64)
    const int g    = lane >> 2;     // groupID 0..7
    const int tg   = lane & 3;      // threadID_in_group

    const int m0 = blockIdx.y * 128;
    const int n0 = blockIdx.x * 128;
    const int NIT = K / 32;

    float acc[2][8][4];
    #pragma unroll
    for (int mt = 0; mt < 2; mt++)
        #pragma unroll
        for (int nt = 0; nt < 8; nt++)
            #pragma unroll
            for (int i = 0; i < 4; i++) acc[mt][nt][i] = 0.f;

    float4 ra[4], rb[4];
    g2r_tile(A, B, m0, n0, 0, K, N, t, ra, rb);
    r2s_tile(sA, sB, t, ra, rb);
    __syncthreads();

    for (int kt = 0; kt < NIT; kt++) {
        const int cur = kt & 1;
        if (kt + 1 < NIT)
            g2r_tile(A, B, m0, n0, (kt + 1) * 32, K, N, t, ra, rb);

        const float* cA = sA + cur * SA_SZ;
        const float* cB = sB + cur * SB_SZ;

        #pragma unroll
        for (int ks = 0; ks < 4; ks++) {
            const int k = ks * 8;
            uint32_t af[2][4];
            #pragma unroll
            for (int mt = 0; mt < 2; mt++) {
                int rbase = wm * 32 + mt * 16;
                af[mt][0] = __float_as_uint(cA[(rbase + g)     * AST + k + tg]);
                af[mt][1] = __float_as_uint(cA[(rbase + g + 8) * AST + k + tg]);
                af[mt][2] = __float_as_uint(cA[(rbase + g)     * AST + k + tg + 4]);
                af[mt][3] = __float_as_uint(cA[(rbase + g + 8) * AST + k + tg + 4]);
            }
            uint32_t bf[8][2];
            #pragma unroll
            for (int nt = 0; nt < 8; nt++) {
                int col = wn * 64 + nt * 8 + g;
                bf[nt][0] = __float_as_uint(cB[(k + tg)     * BST + col]);
                bf[nt][1] = __float_as_uint(cB[(k + tg + 4) * BST + col]);
            }
            #pragma unroll
            for (int mt = 0; mt < 2; mt++)
                #pragma unroll
                for (int nt = 0; nt < 8; nt++)
                    MMA8(acc[mt][nt], af[mt], bf[nt]);
        }

        if (kt + 1 < NIT)
            r2s_tile(sA + (1 - cur) * SA_SZ, sB + (1 - cur) * SB_SZ, t, ra, rb);
        __syncthreads();
    }

    // epilogue
    #pragma unroll
    for (int mt = 0; mt < 2; mt++) {
        #pragma unroll
        for (int nt = 0; nt < 8; nt++) {
            int r0 = m0 + wm * 32 + mt * 16 + g;
            int c0 = n0 + wn * 64 + nt * 8 + tg * 2;
            *(float2*)(C + (size_t)r0 * N + c0)       = make_float2(acc[mt][nt][0], acc[mt][nt][1]);
            *(float2*)(C + (size_t)(r0 + 8) * N + c0) = make_float2(acc[mt][nt][2], acc[mt][nt][3]);
        }
    }
}

// ---------------------------------------------------------------------------
// RoPE (interleaved pairs): x layout [B*S, nheads*128]
// ---------------------------------------------------------------------------
__global__ void rope_kernel(float* __restrict__ x,
                            const float* __restrict__ cosT,
                            const float* __restrict__ sinT,
                            const int* __restrict__ start_pos,
                            int nheads)
{
    int idx = blockIdx.x * blockDim.x + threadIdx.x;
    int total = BB * SS * nheads * (HD / 2);
    if (idx >= total) return;
    int p = idx & 63;
    int h = (idx >> 6) % nheads;
    int srow = (idx / (64 * nheads)) % SS;
    int b = idx / (64 * nheads * SS);
    int pos = start_pos[0] + srow;
    float c = cosT[pos * 64 + p];
    float s = sinT[pos * 64 + p];
    size_t base = ((size_t)(b * SS + srow) * nheads + h) * HD + 2 * p;
    float xr = x[base];
    float xi = x[base + 1];
    x[base]     = xr * c - xi * s;
    x[base + 1] = xr * s + xi * c;
}

// ---------------------------------------------------------------------------
// Attention (SIMT, unchanged — R6 target)
// ---------------------------------------------------------------------------
#define QSTR 132
#define PSTR 68
#define ATTN_SMEM ((64*QSTR*3 + 64*PSTR) * 4)

__global__ __launch_bounds__(256) void attn_kernel(
    const float* __restrict__ q, const float* __restrict__ k,
    const float* __restrict__ v, float* __restrict__ out)
{
    extern __shared__ float sm[];
    float* sQ = sm;
    float* sK = sQ + 64 * QSTR;
    float* sV = sK + 64 * QSTR;
    float* sP = sV + 64 * QSTR;

    const int tid = threadIdx.x;
    const int row = tid >> 2;
    const int sub = tid & 3;

    const int qt = blockIdx.x;
    const int hq = blockIdx.y;
    const int b  = blockIdx.z;
    const int hk = hq >> 2;

    const float* qbase = q + ((size_t)(b * SS + qt * 64)) * (NH * HD) + hq * HD;
    const float* kbase = k + ((size_t)(b * SS)) * (NKV * HD) + hk * HD;
    const float* vbase = v + ((size_t)(b * SS)) * (NKV * HD) + hk * HD;

    #pragma unroll
    for (int i = 0; i < 8; i++) {
        int idx = tid + i * 256;
        int r = idx >> 5;
        int c4 = idx & 31;
        float4 val = *(const float4*)(qbase + (size_t)r * (NH * HD) + c4 * 4);
        *(float4*)(sQ + r * QSTR + c4 * 4) = val;
    }

    float o[32];
    #pragma unroll
    for (int i = 0; i < 32; i++) o[i] = 0.f;
    float m = -3.0e38f;
    float l = 0.f;

    for (int kt = 0; kt < SS / 64; kt++) {
        #pragma unroll
        for (int i = 0; i < 8; i++) {
            int idx = tid + i * 256;
            int r = idx >> 5;
            int c4 = idx & 31;
            size_t goff = (size_t)(kt * 64 + r) * (NKV * HD) + c4 * 4;
            *(float4*)(sK + r * QSTR + c4 * 4) = *(const float4*)(kbase + goff);
            *(float4*)(sV + r * QSTR + c4 * 4) = *(const float4*)(vbase + goff);
        }
        __syncthreads();

        float s[16];
        #pragma unroll
        for (int j = 0; j < 16; j++) s[j] = 0.f;
        const float4* q4p = (const float4*)(sQ + row * QSTR);
        for (int c4 = 0; c4 < 32; c4++) {
            float4 q4 = q4p[c4];
            #pragma unroll
            for (int j = 0; j < 16; j++) {
                int ki = sub + 4 * j;
                float4 k4 = *(const float4*)(sK + ki * QSTR + c4 * 4);
                s[j] = fmaf(q4.x, k4.x, s[j]);
                s[j] = fmaf(q4.y, k4.y, s[j]);
                s[j] = fmaf(q4.z, k4.z, s[j]);
                s[j] = fmaf(q4.w, k4.w, s[j]);
            }
        }

        float tmax = -3.0e38f;
        #pragma unroll
        for (int j = 0; j < 16; j++) {
            s[j] *= SOFT_SCALE;
            tmax = fmaxf(tmax, s[j]);
        }
        tmax = fmaxf(tmax, __shfl_xor_sync(0xffffffffu, tmax, 1));
        tmax = fmaxf(tmax, __shfl_xor_sync(0xffffffffu, tmax, 2));
        float nm = fmaxf(m, tmax);
        float corr = __expf(m - nm);
        float lsum = 0.f;
        #pragma unroll
        for (int j = 0; j < 16; j++) {
            float p = __expf(s[j] - nm);
            lsum += p;
            sP[row * PSTR + sub + 4 * j] = p;
        }
        lsum += __shfl_xor_sync(0xffffffffu, lsum, 1);
        lsum += __shfl_xor_sync(0xffffffffu, lsum, 2);
        l = l * corr + lsum;
        m = nm;
        #pragma unroll
        for (int i = 0; i < 32; i++) o[i] *= corr;
        __syncwarp();

        for (int kk = 0; kk < 64; kk++) {
            float p = sP[row * PSTR + kk];
            const float* vrow = sV + kk * QSTR;
            #pragma unroll
            for (int i = 0; i < 8; i++) {
                float4 v4 = *(const float4*)(vrow + (i * 4 + sub) * 4);
                o[i * 4 + 0] = fmaf(p, v4.x, o[i * 4 + 0]);
                o[i * 4 + 1] = fmaf(p, v4.y, o[i * 4 + 1]);
                o[i * 4 + 2] = fmaf(p, v4.z, o[i * 4 + 2]);
                o[i * 4 + 3] = fmaf(p, v4.w, o[i * 4 + 3]);
            }
        }
        __syncthreads();
    }

    float inv = 1.f / l;
    size_t orow = ((size_t)(b * SS + qt * 64 + row)) * (NH * HD) + hq * HD;
    #pragma unroll
    for (int i = 0; i < 8; i++) {
        float4 val = {o[i*4+0] * inv, o[i*4+1] * inv, o[i*4+2] * inv, o[i*4+3] * inv};
        *(float4*)(out + orow + (i * 4 + sub) * 4) = val;
    }
}

// ---------------------------------------------------------------------------
extern "C" void kernel_launch(void* const* d_in, const int* in_sizes, int n_in,
                              void* d_out, int out_size)
{
    const float* x         = (const float*)d_in[0];
    const int*   start_pos = (const int*)d_in[1];
    const float* cosT      = (const float*)d_in[2];
    const float* sinT      = (const float*)d_in[3];
    const float* wq        = (const float*)d_in[4];
    const float* wk        = (const float*)d_in[5];
    const float* wv        = (const float*)d_in[6];
    const float* wo        = (const float*)d_in[7];
    float* out = (float*)d_out;

    float *q, *k, *v, *attn;
    cudaGetSymbolAddress((void**)&q,    g_q);
    cudaGetSymbolAddress((void**)&k,    g_k);
    cudaGetSymbolAddress((void**)&v,    g_v);
    cudaGetSymbolAddress((void**)&attn, g_attn);

    cudaFuncSetAttribute(mma_gemm, cudaFuncAttributeMaxDynamicSharedMemorySize, GEMM_SMEM);

    // QKV projections (tf32 mma.sync; B consumed row-major [K,N] directly)
    mma_gemm<<<dim3((NH*HD)/128,  MROWS/128), 256, GEMM_SMEM>>>(x, wq, q, MROWS, NH*HD,  DIM);
    mma_gemm<<<dim3((NKV*HD)/128, MROWS/128), 256, GEMM_SMEM>>>(x, wk, k, MROWS, NKV*HD, DIM);
    mma_gemm<<<dim3((NKV*HD)/128, MROWS/128), 256, GEMM_SMEM>>>(x, wv, v, MROWS, NKV*HD, DIM);

    // RoPE
    {
        int totq = BB * SS * NH  * (HD / 2);
        int totk = BB * SS * NKV * (HD / 2);
        rope_kernel<<<(totq + 255) / 256, 256>>>(q, cosT, sinT, start_pos, NH);
        rope_kernel<<<(totk + 255) / 256, 256>>>(k, cosT, sinT, start_pos, NKV);
    }

    // attention
    cudaFuncSetAttribute(attn_kernel, cudaFuncAttributeMaxDynamicSharedMemorySize, ATTN_SMEM);
    attn_kernel<<<dim3(SS/64, NH, BB), 256, ATTN_SMEM>>>(q, k, v, attn);

    // output projection
    mma_gemm<<<dim3(DIM/128, MROWS/128), 256, GEMM_SMEM>>>(attn, wo, out, MROWS, DIM, DIM);
}

// round 7
// speedup vs baseline: 4.0043x; 2.7569x over previous
#include <cuda_runtime.h>
#include <cuda_bf16.h>
#include <cstdint>
#include <math.h>

// Problem constants
#define BB 2
#define SS 2048
#define DIM 4096
#define NH 32
#define NKV 8
#define HD 128
#define MROWS (BB*SS)          // 4096
#define SOFT_SCALE 0.08838834764831845f  // 1/sqrt(128)

// Scratch (allocation-free rule: __device__ globals)
__device__ float g_q[(size_t)MROWS * NH * HD];     // 64 MB
__device__ float g_k[(size_t)MROWS * NKV * HD];    // 16 MB
__device__ float g_v[(size_t)MROWS * NKV * HD];    // 16 MB
__device__ float g_attn[(size_t)MROWS * NH * HD];  // 64 MB

__device__ __forceinline__ float to_tf32(float x) {
    float y;
    asm("cvt.rna.tf32.f32 %0, %1;" : "=f"(y) : "f"(x));
    return y;
}

// m16n8k8 tf32 mma (legacy path — valid on base sm_103 target)
#define MMA8(d, a, b) \
    asm volatile("mma.sync.aligned.m16n8k8.row.col.f32.tf32.tf32.f32 " \
        "{%0,%1,%2,%3}, {%4,%5,%6,%7}, {%8,%9}, {%0,%1,%2,%3};" \
        : "+f"((d)[0]), "+f"((d)[1]), "+f"((d)[2]), "+f"((d)[3]) \
        : "r"((a)[0]), "r"((a)[1]), "r"((a)[2]), "r"((a)[3]), \
          "r"((b)[0]), "r"((b)[1]))

// ---------------------------------------------------------------------------
// tf32 mma.sync GEMM: C[M,N] = A[M,K] @ B[K,N]  (both row-major)
// BM=BN=128, BK=32, 256 threads (8 warps, each 32x64).
// ---------------------------------------------------------------------------
#define AST 36
#define BST 136
#define SA_SZ (128 * AST)     // floats per stage
#define SB_SZ (32 * BST)
#define GEMM_SMEM ((2 * (SA_SZ + SB_SZ)) * 4)   // 71680 bytes

__device__ __forceinline__ void g2r_tile(const float* __restrict__ A,
                                         const float* __restrict__ B,
                                         int m0, int n0, int k0, int K, int N,
                                         int t, float4* ra, float4* rb)
{
    #pragma unroll
    for (int i = 0; i < 4; i++) {           // A: 128 x 32
        int idx = i * 256 + t;
        int r = idx >> 3, c = idx & 7;
        ra[i] = *(const float4*)(A + (size_t)(m0 + r) * K + k0 + c * 4);
    }
    #pragma unroll
    for (int i = 0; i < 4; i++) {           // B: 32 x 128
        int idx = i * 256 + t;
        int r = idx >> 5, c = idx & 31;
        rb[i] = *(const float4*)(B + (size_t)(k0 + r) * N + n0 + c * 4);
    }
}

__device__ __forceinline__ void r2s_tile(float* sA, float* sB, int t,
                                         const float4* ra, const float4* rb)
{
    #pragma unroll
    for (int i = 0; i < 4; i++) {
        int idx = i * 256 + t;
        int r = idx >> 3, c = idx & 7;
        float4 v = ra[i];
        v.x = to_tf32(v.x); v.y = to_tf32(v.y); v.z = to_tf32(v.z); v.w = to_tf32(v.w);
        *(float4*)(sA + r * AST + c * 4) = v;
    }
    #pragma unroll
    for (int i = 0; i < 4; i++) {
        int idx = i * 256 + t;
        int r = idx >> 5, c = idx & 31;
        float4 v = rb[i];
        v.x = to_tf32(v.x); v.y = to_tf32(v.y); v.z = to_tf32(v.z); v.w = to_tf32(v.w);
        *(float4*)(sB + r * BST + c * 4) = v;
    }
}

__global__ __launch_bounds__(256) void mma_gemm(const float* __restrict__ A,
                                                const float* __restrict__ B,
                                                float* __restrict__ C,
                                                int M, int N, int K)
{
    extern __shared__ float sm[];
    float* sA = sm;                 // [2][SA_SZ]
    float* sB = sm + 2 * SA_SZ;     // [2][SB_SZ]

    const int t    = threadIdx.x;
    const int wid  = t >> 5;
    const int lane = t & 31;
    const int wm   = wid >> 1;      // 0..3  (rows wm*32)
    const int wn   = wid & 1;       // 0..1  (cols wn*64)
    const int g    = lane >> 2;     // groupID 0..7
    const int tg   = lane & 3;      // threadID_in_group

    const int m0 = blockIdx.y * 128;
    const int n0 = blockIdx.x * 128;
    const int NIT = K / 32;

    float acc[2][8][4];
    #pragma unroll
    for (int mt = 0; mt < 2; mt++)
        #pragma unroll
        for (int nt = 0; nt < 8; nt++)
            #pragma unroll
            for (int i = 0; i < 4; i++) acc[mt][nt][i] = 0.f;

    float4 ra[4], rb[4];
    g2r_tile(A, B, m0, n0, 0, K, N, t, ra, rb);
    r2s_tile(sA, sB, t, ra, rb);
    __syncthreads();

    for (int kt = 0; kt < NIT; kt++) {
        const int cur = kt & 1;
        if (kt + 1 < NIT)
            g2r_tile(A, B, m0, n0, (kt + 1) * 32, K, N, t, ra, rb);

        const float* cA = sA + cur * SA_SZ;
        const float* cB = sB + cur * SB_SZ;

        #pragma unroll
        for (int ks = 0; ks < 4; ks++) {
            const int k = ks * 8;
            uint32_t af[2][4];
            #pragma unroll
            for (int mt = 0; mt < 2; mt++) {
                int rbase = wm * 32 + mt * 16;
                af[mt][0] = __float_as_uint(cA[(rbase + g)     * AST + k + tg]);
                af[mt][1] = __float_as_uint(cA[(rbase + g + 8) * AST + k + tg]);
                af[mt][2] = __float_as_uint(cA[(rbase + g)     * AST + k + tg + 4]);
                af[mt][3] = __float_as_uint(cA[(rbase + g + 8) * AST + k + tg + 4]);
            }
            uint32_t bf[8][2];
            #pragma unroll
            for (int nt = 0; nt < 8; nt++) {
                int col = wn * 64 + nt * 8 + g;
                bf[nt][0] = __float_as_uint(cB[(k + tg)     * BST + col]);
                bf[nt][1] = __float_as_uint(cB[(k + tg + 4) * BST + col]);
            }
            #pragma unroll
            for (int mt = 0; mt < 2; mt++)
                #pragma unroll
                for (int nt = 0; nt < 8; nt++)
                    MMA8(acc[mt][nt], af[mt], bf[nt]);
        }

        if (kt + 1 < NIT)
            r2s_tile(sA + (1 - cur) * SA_SZ, sB + (1 - cur) * SB_SZ, t, ra, rb);
        __syncthreads();
    }

    // epilogue
    #pragma unroll
    for (int mt = 0; mt < 2; mt++) {
        #pragma unroll
        for (int nt = 0; nt < 8; nt++) {
            int r0 = m0 + wm * 32 + mt * 16 + g;
            int c0 = n0 + wn * 64 + nt * 8 + tg * 2;
            *(float2*)(C + (size_t)r0 * N + c0)       = make_float2(acc[mt][nt][0], acc[mt][nt][1]);
            *(float2*)(C + (size_t)(r0 + 8) * N + c0) = make_float2(acc[mt][nt][2], acc[mt][nt][3]);
        }
    }
}

// ---------------------------------------------------------------------------
// RoPE (interleaved pairs): x layout [B*S, nheads*128]
// ---------------------------------------------------------------------------
__global__ void rope_kernel(float* __restrict__ x,
                            const float* __restrict__ cosT,
                            const float* __restrict__ sinT,
                            const int* __restrict__ start_pos,
                            int nheads)
{
    int idx = blockIdx.x * blockDim.x + threadIdx.x;
    int total = BB * SS * nheads * (HD / 2);
    if (idx >= total) return;
    int p = idx & 63;
    int h = (idx >> 6) % nheads;
    int srow = (idx / (64 * nheads)) % SS;
    int b = idx / (64 * nheads * SS);
    int pos = start_pos[0] + srow;
    float c = cosT[pos * 64 + p];
    float s = sinT[pos * 64 + p];
    size_t base = ((size_t)(b * SS + srow) * nheads + h) * HD + 2 * p;
    float xr = x[base];
    float xi = x[base + 1];
    x[base]     = xr * c - xi * s;
    x[base + 1] = xr * s + xi * c;
}

// ---------------------------------------------------------------------------
// Flash attention with tf32 mma.sync.
// CTA: 128 q-rows x (one q-head) x batch. 256 threads, 8 warps.
// Warp w owns q-rows [w*16, w*16+16) — full softmax row inside one warp.
// K-tile = 64 keys. QK^T: m16 x n64 (8 frags) x k128; PV: m16 x n128 (16) x k64.
// Strides: Q/K 132, V 136, P 68 — all conflict-free for their access patterns.
// ---------------------------------------------------------------------------
#define AQSTR 132
#define AKSTR 132
#define AVSTR 136
#define APSTR 68
#define ATTN_SMEM ((128*AQSTR + 64*AKSTR + 64*AVSTR + 128*APSTR) * 4)  // 171008

__global__ __launch_bounds__(256, 1) void attn_mma(
    const float* __restrict__ q, const float* __restrict__ k,
    const float* __restrict__ v, float* __restrict__ out)
{
    extern __shared__ float sm[];
    float* sQ = sm;                       // 128 x 132
    float* sK = sQ + 128 * AQSTR;         // 64 x 132
    float* sV = sK + 64 * AKSTR;          // 64 x 136
    float* sP = sV + 64 * AVSTR;          // 128 x 68

    const int t    = threadIdx.x;
    const int wid  = t >> 5;
    const int lane = t & 31;
    const int g    = lane >> 2;     // 0..7
    const int tg   = lane & 3;      // 0..3
    const int wrow = wid * 16;

    const int qt = blockIdx.x;      // 0..15
    const int hq = blockIdx.y;      // 0..31
    const int b  = blockIdx.z;      // 0..1
    const int hk = hq >> 2;

    const float* qbase = q + ((size_t)(b * SS + qt * 128)) * (NH * HD) + hq * HD;
    const float* kbase = k + ((size_t)(b * SS)) * (NKV * HD) + hk * HD;
    const float* vbase = v + ((size_t)(b * SS)) * (NKV * HD) + hk * HD;

    // load Q tile 128x128 (tf32-rounded)
    #pragma unroll
    for (int i = 0; i < 16; i++) {
        int idx = i * 256 + t;
        int r = idx >> 5, c4 = idx & 31;
        float4 val = *(const float4*)(qbase + (size_t)r * (NH * HD) + c4 * 4);
        val.x = to_tf32(val.x); val.y = to_tf32(val.y);
        val.z = to_tf32(val.z); val.w = to_tf32(val.w);
        *(float4*)(sQ + r * AQSTR + c4 * 4) = val;
    }

    float o[16][4];
    #pragma unroll
    for (int nt = 0; nt < 16; nt++)
        #pragma unroll
        for (int j = 0; j < 4; j++) o[nt][j] = 0.f;
    float m0 = -3.0e38f, m1 = -3.0e38f;
    float l0 = 0.f, l1 = 0.f;

    for (int kt = 0; kt < SS / 64; kt++) {
        __syncthreads();   // previous PV done reading sK/sV
        #pragma unroll
        for (int i = 0; i < 8; i++) {
            int idx = i * 256 + t;
            int r = idx >> 5, c4 = idx & 31;
            size_t goff = (size_t)(kt * 64 + r) * (NKV * HD) + c4 * 4;
            float4 kv = *(const float4*)(kbase + goff);
            kv.x = to_tf32(kv.x); kv.y = to_tf32(kv.y);
            kv.z = to_tf32(kv.z); kv.w = to_tf32(kv.w);
            *(float4*)(sK + r * AKSTR + c4 * 4) = kv;
            float4 vv = *(const float4*)(vbase + goff);
            vv.x = to_tf32(vv.x); vv.y = to_tf32(vv.y);
            vv.z = to_tf32(vv.z); vv.w = to_tf32(vv.w);
            *(float4*)(sV + r * AVSTR + c4 * 4) = vv;
        }
        __syncthreads();

        // ---- QK^T: 16 rows x 64 keys ----
        float sacc[8][4];
        #pragma unroll
        for (int nt = 0; nt < 8; nt++)
            #pragma unroll
            for (int j = 0; j < 4; j++) sacc[nt][j] = 0.f;

        #pragma unroll
        for (int ks = 0; ks < 16; ks++) {
            const int kk = ks * 8;
            uint32_t af[4];
            af[0] = __float_as_uint(sQ[(wrow + g)     * AQSTR + kk + tg]);
            af[1] = __float_as_uint(sQ[(wrow + g + 8) * AQSTR + kk + tg]);
            af[2] = __float_as_uint(sQ[(wrow + g)     * AQSTR + kk + tg + 4]);
            af[3] = __float_as_uint(sQ[(wrow + g + 8) * AQSTR + kk + tg + 4]);
            #pragma unroll
            for (int nt = 0; nt < 8; nt++) {
                uint32_t bf[2];
                const int n = nt * 8 + g;
                bf[0] = __float_as_uint(sK[n * AKSTR + kk + tg]);
                bf[1] = __float_as_uint(sK[n * AKSTR + kk + tg + 4]);
                MMA8(sacc[nt], af, bf);
            }
        }

        // ---- online softmax (rows g and g+8 of this warp's 16) ----
        float tmax0 = -3.0e38f, tmax1 = -3.0e38f;
        #pragma unroll
        for (int nt = 0; nt < 8; nt++) {
            sacc[nt][0] *= SOFT_SCALE; sacc[nt][1] *= SOFT_SCALE;
            sacc[nt][2] *= SOFT_SCALE; sacc[nt][3] *= SOFT_SCALE;
            tmax0 = fmaxf(tmax0, fmaxf(sacc[nt][0], sacc[nt][1]));
            tmax1 = fmaxf(tmax1, fmaxf(sacc[nt][2], sacc[nt][3]));
        }
        tmax0 = fmaxf(tmax0, __shfl_xor_sync(0xffffffffu, tmax0, 1));
        tmax0 = fmaxf(tmax0, __shfl_xor_sync(0xffffffffu, tmax0, 2));
        tmax1 = fmaxf(tmax1, __shfl_xor_sync(0xffffffffu, tmax1, 1));
        tmax1 = fmaxf(tmax1, __shfl_xor_sync(0xffffffffu, tmax1, 2));
        const float nm0 = fmaxf(m0, tmax0);
        const float nm1 = fmaxf(m1, tmax1);
        const float corr0 = __expf(m0 - nm0);
        const float corr1 = __expf(m1 - nm1);

        float ls0 = 0.f, ls1 = 0.f;
        #pragma unroll
        for (int nt = 0; nt < 8; nt++) {
            float p0 = to_tf32(__expf(sacc[nt][0] - nm0));
            float p1 = to_tf32(__expf(sacc[nt][1] - nm0));
            float p2 = to_tf32(__expf(sacc[nt][2] - nm1));
            float p3 = to_tf32(__expf(sacc[nt][3] - nm1));
            ls0 += p0 + p1;
            ls1 += p2 + p3;
            *(float2*)(sP + (wrow + g)     * APSTR + nt * 8 + tg * 2) = make_float2(p0, p1);
            *(float2*)(sP + (wrow + g + 8) * APSTR + nt * 8 + tg * 2) = make_float2(p2, p3);
        }
        ls0 += __shfl_xor_sync(0xffffffffu, ls0, 1);
        ls0 += __shfl_xor_sync(0xffffffffu, ls0, 2);
        ls1 += __shfl_xor_sync(0xffffffffu, ls1, 1);
        ls1 += __shfl_xor_sync(0xffffffffu, ls1, 2);
        l0 = l0 * corr0 + ls0;  m0 = nm0;
        l1 = l1 * corr1 + ls1;  m1 = nm1;

        #pragma unroll
        for (int nt = 0; nt < 16; nt++) {
            o[nt][0] *= corr0; o[nt][1] *= corr0;
            o[nt][2] *= corr1; o[nt][3] *= corr1;
        }
        __syncwarp();   // sP rows of this warp produced/consumed by same warp

        // ---- PV: 16 rows x 128 dims x 64 keys ----
        #pragma unroll
        for (int ks = 0; ks < 8; ks++) {
            const int kk = ks * 8;
            uint32_t af[4];
            af[0] = __float_as_uint(sP[(wrow + g)     * APSTR + kk + tg]);
            af[1] = __float_as_uint(sP[(wrow + g + 8) * APSTR + kk + tg]);
            af[2] = __float_as_uint(sP[(wrow + g)     * APSTR + kk + tg + 4]);
            af[3] = __float_as_uint(sP[(wrow + g + 8) * APSTR + kk + tg + 4]);
            #pragma unroll
            for (int nt = 0; nt < 16; nt++) {
                uint32_t bf[2];
                const int n = nt * 8 + g;
                bf[0] = __float_as_uint(sV[(kk + tg)     * AVSTR + n]);
                bf[1] = __float_as_uint(sV[(kk + tg + 4) * AVSTR + n]);
                MMA8(o[nt], af, bf);
            }
        }
        __syncwarp();
    }

    // epilogue
    const float inv0 = 1.f / l0;
    const float inv1 = 1.f / l1;
    const size_t r0 = (size_t)(b * SS + qt * 128 + wrow + g);
    const size_t r1 = r0 + 8;
    #pragma unroll
    for (int nt = 0; nt < 16; nt++) {
        const int c = hq * HD + nt * 8 + tg * 2;
        *(float2*)(out + r0 * (NH * HD) + c) = make_float2(o[nt][0] * inv0, o[nt][1] * inv0);
        *(float2*)(out + r1 * (NH * HD) + c) = make_float2(o[nt][2] * inv1, o[nt][3] * inv1);
    }
}

// ---------------------------------------------------------------------------
extern "C" void kernel_launch(void* const* d_in, const int* in_sizes, int n_in,
                              void* d_out, int out_size)
{
    const float* x         = (const float*)d_in[0];
    const int*   start_pos = (const int*)d_in[1];
    const float* cosT      = (const float*)d_in[2];
    const float* sinT      = (const float*)d_in[3];
    const float* wq        = (const float*)d_in[4];
    const float* wk        = (const float*)d_in[5];
    const float* wv        = (const float*)d_in[6];
    const float* wo        = (const float*)d_in[7];
    float* out = (float*)d_out;

    float *q, *k, *v, *attn;
    cudaGetSymbolAddress((void**)&q,    g_q);
    cudaGetSymbolAddress((void**)&k,    g_k);
    cudaGetSymbolAddress((void**)&v,    g_v);
    cudaGetSymbolAddress((void**)&attn, g_attn);

    cudaFuncSetAttribute(mma_gemm, cudaFuncAttributeMaxDynamicSharedMemorySize, GEMM_SMEM);

    // QKV projections (tf32 mma.sync; B consumed row-major [K,N] directly)
    mma_gemm<<<dim3((NH*HD)/128,  MROWS/128), 256, GEMM_SMEM>>>(x, wq, q, MROWS, NH*HD,  DIM);
    mma_gemm<<<dim3((NKV*HD)/128, MROWS/128), 256, GEMM_SMEM>>>(x, wk, k, MROWS, NKV*HD, DIM);
    mma_gemm<<<dim3((NKV*HD)/128, MROWS/128), 256, GEMM_SMEM>>>(x, wv, v, MROWS, NKV*HD, DIM);

    // RoPE
    {
        int totq = BB * SS * NH  * (HD / 2);
        int totk = BB * SS * NKV * (HD / 2);
        rope_kernel<<<(totq + 255) / 256, 256>>>(q, cosT, sinT, start_pos, NH);
        rope_kernel<<<(totk + 255) / 256, 256>>>(k, cosT, sinT, start_pos, NKV);
    }

    // attention (tf32 mma flash)
    cudaFuncSetAttribute(attn_mma, cudaFuncAttributeMaxDynamicSharedMemorySize, ATTN_SMEM);
    attn_mma<<<dim3(SS/128, NH, BB), 256, ATTN_SMEM>>>(q, k, v, attn);

    // output projection
    mma_gemm<<<dim3(DIM/128, MROWS/128), 256, GEMM_SMEM>>>(attn, wo, out, MROWS, DIM, DIM);
}

// round 9
// speedup vs baseline: 4.8015x; 1.1991x over previous
#include <cuda_runtime.h>
#include <cuda_bf16.h>
#include <cstdint>
#include <math.h>

// Problem constants
#define BB 2
#define SS 2048
#define DIM 4096
#define NH 32
#define NKV 8
#define HD 128
#define MROWS (BB*SS)          // 4096
#define SOFT_SCALE 0.08838834764831845f  // 1/sqrt(128)

// Scratch (allocation-free rule: __device__ globals)
__device__ float g_q[(size_t)MROWS * NH * HD];     // 64 MB
__device__ float g_k[(size_t)MROWS * NKV * HD];    // 16 MB
__device__ float g_v[(size_t)MROWS * NKV * HD];    // 16 MB
__device__ float g_attn[(size_t)MROWS * NH * HD];  // 64 MB (tf32-rounded by attn epilogue)
// tf32-pre-rounded inputs
__device__ float g_xr[(size_t)MROWS * DIM];        // 64 MB
__device__ float g_wqr[(size_t)DIM * (NH*HD)];     // 64 MB
__device__ float g_wkr[(size_t)DIM * (NKV*HD)];    // 16 MB
__device__ float g_wvr[(size_t)DIM * (NKV*HD)];    // 16 MB
__device__ float g_wor[(size_t)(NH*HD) * DIM];     // 64 MB

__device__ __forceinline__ float to_tf32(float x) {
    float y;
    asm("cvt.rna.tf32.f32 %0, %1;" : "=f"(y) : "f"(x));
    return y;
}
__device__ __forceinline__ uint32_t smem_u32(const void* p) {
    uint32_t a;
    asm("{ .reg .u64 t; cvta.to.shared.u64 t, %1; cvt.u32.u64 %0, t; }" : "=r"(a) : "l"(p));
    return a;
}
__device__ __forceinline__ void cp16(uint32_t dst, const void* src) {
    asm volatile("cp.async.cg.shared.global [%0], [%1], 16;" :: "r"(dst), "l"(src));
}
#define CP_COMMIT() asm volatile("cp.async.commit_group;" ::: "memory")
#define CP_WAIT1()  asm volatile("cp.async.wait_group 1;" ::: "memory")

// m16n8k8 tf32 mma (legacy path — valid on base sm_103 target)
#define MMA8(d, a, b) \
    asm volatile("mma.sync.aligned.m16n8k8.row.col.f32.tf32.tf32.f32 " \
        "{%0,%1,%2,%3}, {%4,%5,%6,%7}, {%8,%9}, {%0,%1,%2,%3};" \
        : "+f"((d)[0]), "+f"((d)[1]), "+f"((d)[2]), "+f"((d)[3]) \
        : "r"((a)[0]), "r"((a)[1]), "r"((a)[2]), "r"((a)[3]), \
          "r"((b)[0]), "r"((b)[1]))

// ---------------------------------------------------------------------------
// Prepass: elementwise tf32 rounding (float4, element count divisible by 4)
// ---------------------------------------------------------------------------
__global__ void round_tf32_kernel(const float* __restrict__ in,
                                  float* __restrict__ out, int n4)
{
    int i = blockIdx.x * blockDim.x + threadIdx.x;
    if (i >= n4) return;
    float4 v = ((const float4*)in)[i];
    v.x = to_tf32(v.x); v.y = to_tf32(v.y);
    v.z = to_tf32(v.z); v.w = to_tf32(v.w);
    ((float4*)out)[i] = v;
}

// ---------------------------------------------------------------------------
// tf32 mma.sync GEMM core: C[M,N] = A[M,K] @ B[K,N], inputs pre-rounded tf32.
// BM=128, BN=256, BK=32; 256 threads, 8 warps of 64x64 (wm = wid>>2, wn = wid&3).
// 3-stage cp.async pipeline, 1 syncthreads/iter.
// sA stride 36 floats, sB stride 264 floats — conflict-free fragment LDS.
// ---------------------------------------------------------------------------
#define GBK 32
#define ASTR 36
#define BSTR 264
#define A_STG (128 * ASTR)          // 4608 floats
#define B_STG (GBK * BSTR)          // 8448 floats
#define STG   (A_STG + B_STG)       // 13056 floats
#define GEMM_SMEM (3 * STG * 4)     // 156672 bytes

__device__ __forceinline__ void gemm_core(const float* __restrict__ A,
                                          const float* __restrict__ B,
                                          float* __restrict__ C,
                                          int M, int N, int K,
                                          int bxn, int bym)
{
    extern __shared__ float sm[];
    const uint32_t smem_base = smem_u32(sm);

    const int t    = threadIdx.x;
    const int wid  = t >> 5;
    const int lane = t & 31;
    const int wm   = wid >> 2;      // 0..1
    const int wn   = wid & 3;       // 0..3
    const int g    = lane >> 2;     // 0..7
    const int tg   = lane & 3;      // 0..3

    const int m0 = bym * 128;
    const int n0 = bxn * 256;
    const int NIT = K / GBK;

    // per-thread staging indices
    const int ar = t >> 3,  ac = t & 7;    // A: 4 chunks, rows ar + i*32
    const int br = t >> 6,  bc = t & 63;   // B: 8 chunks, rows br + i*4

    // ---- pipeline load helper (tile kt into stage st) ----
    auto load_stage = [&](int st, int kt) {
        const uint32_t sa = smem_base + (uint32_t)(st * STG) * 4u;
        const uint32_t sb = sa + (uint32_t)A_STG * 4u;
        const float* Ap = A + (size_t)(m0 + ar) * K + kt * GBK + ac * 4;
        #pragma unroll
        for (int i = 0; i < 4; i++)
            cp16(sa + (ar + i * 32) * (ASTR * 4) + ac * 16,
                 Ap + (size_t)(i * 32) * K);
        const float* Bp = B + (size_t)(kt * GBK + br) * N + n0 + bc * 4;
        #pragma unroll
        for (int i = 0; i < 8; i++)
            cp16(sb + (br + i * 4) * (BSTR * 4) + bc * 16,
                 Bp + (size_t)(i * 4) * N);
    };

    float acc[4][8][4];
    #pragma unroll
    for (int mt = 0; mt < 4; mt++)
        #pragma unroll
        for (int nt = 0; nt < 8; nt++)
            #pragma unroll
            for (int j = 0; j < 4; j++) acc[mt][nt][j] = 0.f;

    load_stage(0, 0); CP_COMMIT();
    load_stage(1, 1); CP_COMMIT();

    for (int kt = 0; kt < NIT; kt++) {
        CP_WAIT1();            // tile kt resident (all but newest group done)
        __syncthreads();       // all warps done with stage being overwritten

        int nxt = kt + 2 < NIT ? kt + 2 : NIT - 1;   // clamped (redundant at tail)
        load_stage((kt + 2) % 3, nxt);
        CP_COMMIT();

        const float* cA = sm + (kt % 3) * STG;
        const float* cB = cA + A_STG;

        #pragma unroll
        for (int ks = 0; ks < 4; ks++) {
            const int kk = ks * 8;
            uint32_t af[4][4];
            #pragma unroll
            for (int mt = 0; mt < 4; mt++) {
                const int rbase = wm * 64 + mt * 16;
                af[mt][0] = __float_as_uint(cA[(rbase + g)     * ASTR + kk + tg]);
                af[mt][1] = __float_as_uint(cA[(rbase + g + 8) * ASTR + kk + tg]);
                af[mt][2] = __float_as_uint(cA[(rbase + g)     * ASTR + kk + tg + 4]);
                af[mt][3] = __float_as_uint(cA[(rbase + g + 8) * ASTR + kk + tg + 4]);
            }
            uint32_t bf[8][2];
            #pragma unroll
            for (int nt = 0; nt < 8; nt++) {
                const int col = wn * 64 + nt * 8 + g;
                bf[nt][0] = __float_as_uint(cB[(kk + tg)     * BSTR + col]);
                bf[nt][1] = __float_as_uint(cB[(kk + tg + 4) * BSTR + col]);
            }
            #pragma unroll
            for (int mt = 0; mt < 4; mt++)
                #pragma unroll
                for (int nt = 0; nt < 8; nt++)
                    MMA8(acc[mt][nt], af[mt], bf[nt]);
        }
    }

    // epilogue
    #pragma unroll
    for (int mt = 0; mt < 4; mt++) {
        #pragma unroll
        for (int nt = 0; nt < 8; nt++) {
            const int r0 = m0 + wm * 64 + mt * 16 + g;
            const int c0 = n0 + wn * 64 + nt * 8 + tg * 2;
            *(float2*)(C + (size_t)r0 * N + c0)       = make_float2(acc[mt][nt][0], acc[mt][nt][1]);
            *(float2*)(C + (size_t)(r0 + 8) * N + c0) = make_float2(acc[mt][nt][2], acc[mt][nt][3]);
        }
    }
}

__global__ __launch_bounds__(256, 1) void mma_gemm(const float* __restrict__ A,
                                                   const float* __restrict__ B,
                                                   float* __restrict__ C,
                                                   int M, int N, int K)
{
    gemm_core(A, B, C, M, N, K, blockIdx.x, blockIdx.y);
}

// Fused K+V projection: grid.x = 8 (4 blocks K, 4 blocks V), N=1024 each
__global__ __launch_bounds__(256, 1) void mma_gemm_kv(const float* __restrict__ A,
                                                      const float* __restrict__ Bk,
                                                      const float* __restrict__ Bv,
                                                      float* __restrict__ Ck,
                                                      float* __restrict__ Cv,
                                                      int M, int K)
{
    const bool isV = blockIdx.x >= 4;
    gemm_core(A, isV ? Bv : Bk, isV ? Cv : Ck,
              M, NKV * HD, K, isV ? blockIdx.x - 4 : blockIdx.x, blockIdx.y);
}

// ---------------------------------------------------------------------------
// RoPE (interleaved pairs): x layout [B*S, nheads*128]
// ---------------------------------------------------------------------------
__global__ void rope_kernel(float* __restrict__ x,
                            const float* __restrict__ cosT,
                            const float* __restrict__ sinT,
                            const int* __restrict__ start_pos,
                            int nheads)
{
    int idx = blockIdx.x * blockDim.x + threadIdx.x;
    int total = BB * SS * nheads * (HD / 2);
    if (idx >= total) return;
    int p = idx & 63;
    int h = (idx >> 6) % nheads;
    int srow = (idx / (64 * nheads)) % SS;
    int b = idx / (64 * nheads * SS);
    int pos = start_pos[0] + srow;
    float c = cosT[pos * 64 + p];
    float s = sinT[pos * 64 + p];
    size_t base = ((size_t)(b * SS + srow) * nheads + h) * HD + 2 * p;
    float xr = x[base];
    float xi = x[base + 1];
    x[base]     = xr * c - xi * s;
    x[base + 1] = xr * s + xi * c;
}

// ---------------------------------------------------------------------------
// Flash attention with tf32 mma.sync (unchanged numerics from R7; epilogue now
// writes tf32-rounded values so the wo-GEMM can cp.async them directly).
// ---------------------------------------------------------------------------
#define AQSTR 132
#define AKSTR 132
#define AVSTR 136
#define APSTR 68
#define ATTN_SMEM ((128*AQSTR + 64*AKSTR + 64*AVSTR + 128*APSTR) * 4)  // 171008

__global__ __launch_bounds__(256, 1) void attn_mma(
    const float* __restrict__ q, const float* __restrict__ k,
    const float* __restrict__ v, float* __restrict__ out)
{
    extern __shared__ float sm[];
    float* sQ = sm;                       // 128 x 132
    float* sK = sQ + 128 * AQSTR;         // 64 x 132
    float* sV = sK + 64 * AKSTR;          // 64 x 136
    float* sP = sV + 64 * AVSTR;          // 128 x 68

    const int t    = threadIdx.x;
    const int wid  = t >> 5;
    const int lane = t & 31;
    const int g    = lane >> 2;     // 0..7
    const int tg   = lane & 3;      // 0..3
    const int wrow = wid * 16;

    const int qt = blockIdx.x;      // 0..15
    const int hq = blockIdx.y;      // 0..31
    const int b  = blockIdx.z;      // 0..1
    const int hk = hq >> 2;

    const float* qbase = q + ((size_t)(b * SS + qt * 128)) * (NH * HD) + hq * HD;
    const float* kbase = k + ((size_t)(b * SS)) * (NKV * HD) + hk * HD;
    const float* vbase = v + ((size_t)(b * SS)) * (NKV * HD) + hk * HD;

    // load Q tile 128x128 (tf32-rounded)
    #pragma unroll
    for (int i = 0; i < 16; i++) {
        int idx = i * 256 + t;
        int r = idx >> 5, c4 = idx & 31;
        float4 val = *(const float4*)(qbase + (size_t)r * (NH * HD) + c4 * 4);
        val.x = to_tf32(val.x); val.y = to_tf32(val.y);
        val.z = to_tf32(val.z); val.w = to_tf32(val.w);
        *(float4*)(sQ + r * AQSTR + c4 * 4) = val;
    }

    float o[16][4];
    #pragma unroll
    for (int nt = 0; nt < 16; nt++)
        #pragma unroll
        for (int j = 0; j < 4; j++) o[nt][j] = 0.f;
    float m0 = -3.0e38f, m1 = -3.0e38f;
    float l0 = 0.f, l1 = 0.f;

    for (int kt = 0; kt < SS / 64; kt++) {
        __syncthreads();   // previous PV done reading sK/sV
        #pragma unroll
        for (int i = 0; i < 8; i++) {
            int idx = i * 256 + t;
            int r = idx >> 5, c4 = idx & 31;
            size_t goff = (size_t)(kt * 64 + r) * (NKV * HD) + c4 * 4;
            float4 kv = *(const float4*)(kbase + goff);
            kv.x = to_tf32(kv.x); kv.y = to_tf32(kv.y);
            kv.z = to_tf32(kv.z); kv.w = to_tf32(kv.w);
            *(float4*)(sK + r * AKSTR + c4 * 4) = kv;
            float4 vv = *(const float4*)(vbase + goff);
            vv.x = to_tf32(vv.x); vv.y = to_tf32(vv.y);
            vv.z = to_tf32(vv.z); vv.w = to_tf32(vv.w);
            *(float4*)(sV + r * AVSTR + c4 * 4) = vv;
        }
        __syncthreads();

        // ---- QK^T ----
        float sacc[8][4];
        #pragma unroll
        for (int nt = 0; nt < 8; nt++)
            #pragma unroll
            for (int j = 0; j < 4; j++) sacc[nt][j] = 0.f;

        #pragma unroll
        for (int ks = 0; ks < 16; ks++) {
            const int kk = ks * 8;
            uint32_t af[4];
            af[0] = __float_as_uint(sQ[(wrow + g)     * AQSTR + kk + tg]);
            af[1] = __float_as_uint(sQ[(wrow + g + 8) * AQSTR + kk + tg]);
            af[2] = __float_as_uint(sQ[(wrow + g)     * AQSTR + kk + tg + 4]);
            af[3] = __float_as_uint(sQ[(wrow + g + 8) * AQSTR + kk + tg + 4]);
            #pragma unroll
            for (int nt = 0; nt < 8; nt++) {
                uint32_t bf[2];
                const int n = nt * 8 + g;
                bf[0] = __float_as_uint(sK[n * AKSTR + kk + tg]);
                bf[1] = __float_as_uint(sK[n * AKSTR + kk + tg + 4]);
                MMA8(sacc[nt], af, bf);
            }
        }

        // ---- online softmax ----
        float tmax0 = -3.0e38f, tmax1 = -3.0e38f;
        #pragma unroll
        for (int nt = 0; nt < 8; nt++) {
            sacc[nt][0] *= SOFT_SCALE; sacc[nt][1] *= SOFT_SCALE;
            sacc[nt][2] *= SOFT_SCALE; sacc[nt][3] *= SOFT_SCALE;
            tmax0 = fmaxf(tmax0, fmaxf(sacc[nt][0], sacc[nt][1]));
            tmax1 = fmaxf(tmax1, fmaxf(sacc[nt][2], sacc[nt][3]));
        }
        tmax0 = fmaxf(tmax0, __shfl_xor_sync(0xffffffffu, tmax0, 1));
        tmax0 = fmaxf(tmax0, __shfl_xor_sync(0xffffffffu, tmax0, 2));
        tmax1 = fmaxf(tmax1, __shfl_xor_sync(0xffffffffu, tmax1, 1));
        tmax1 = fmaxf(tmax1, __shfl_xor_sync(0xffffffffu, tmax1, 2));
        const float nm0 = fmaxf(m0, tmax0);
        const float nm1 = fmaxf(m1, tmax1);
        const float corr0 = __expf(m0 - nm0);
        const float corr1 = __expf(m1 - nm1);

        float ls0 = 0.f, ls1 = 0.f;
        #pragma unroll
        for (int nt = 0; nt < 8; nt++) {
            float p0 = to_tf32(__expf(sacc[nt][0] - nm0));
            float p1 = to_tf32(__expf(sacc[nt][1] - nm0));
            float p2 = to_tf32(__expf(sacc[nt][2] - nm1));
            float p3 = to_tf32(__expf(sacc[nt][3] - nm1));
            ls0 += p0 + p1;
            ls1 += p2 + p3;
            *(float2*)(sP + (wrow + g)     * APSTR + nt * 8 + tg * 2) = make_float2(p0, p1);
            *(float2*)(sP + (wrow + g + 8) * APSTR + nt * 8 + tg * 2) = make_float2(p2, p3);
        }
        ls0 += __shfl_xor_sync(0xffffffffu, ls0, 1);
        ls0 += __shfl_xor_sync(0xffffffffu, ls0, 2);
        ls1 += __shfl_xor_sync(0xffffffffu, ls1, 1);
        ls1 += __shfl_xor_sync(0xffffffffu, ls1, 2);
        l0 = l0 * corr0 + ls0;  m0 = nm0;
        l1 = l1 * corr1 + ls1;  m1 = nm1;

        #pragma unroll
        for (int nt = 0; nt < 16; nt++) {
            o[nt][0] *= corr0; o[nt][1] *= corr0;
            o[nt][2] *= corr1; o[nt][3] *= corr1;
        }
        __syncwarp();

        // ---- PV ----
        #pragma unroll
        for (int ks = 0; ks < 8; ks++) {
            const int kk = ks * 8;
            uint32_t af[4];
            af[0] = __float_as_uint(sP[(wrow + g)     * APSTR + kk + tg]);
            af[1] = __float_as_uint(sP[(wrow + g + 8) * APSTR + kk + tg]);
            af[2] = __float_as_uint(sP[(wrow + g)     * APSTR + kk + tg + 4]);
            af[3] = __float_as_uint(sP[(wrow + g + 8) * APSTR + kk + tg + 4]);
            #pragma unroll
            for (int nt = 0; nt < 16; nt++) {
                uint32_t bf[2];
                const int n = nt * 8 + g;
                bf[0] = __float_as_uint(sV[(kk + tg)     * AVSTR + n]);
                bf[1] = __float_as_uint(sV[(kk + tg + 4) * AVSTR + n]);
                MMA8(o[nt], af, bf);
            }
        }
        __syncwarp();
    }

    // epilogue — write tf32-rounded (same values the wo-GEMM previously rounded)
    const float inv0 = 1.f / l0;
    const float inv1 = 1.f / l1;
    const size_t r0 = (size_t)(b * SS + qt * 128 + wrow + g);
    const size_t r1 = r0 + 8;
    #pragma unroll
    for (int nt = 0; nt < 16; nt++) {
        const int c = hq * HD + nt * 8 + tg * 2;
        *(float2*)(out + r0 * (NH * HD) + c) =
            make_float2(to_tf32(o[nt][0] * inv0), to_tf32(o[nt][1] * inv0));
        *(float2*)(out + r1 * (NH * HD) + c) =
            make_float2(to_tf32(o[nt][2] * inv1), to_tf32(o[nt][3] * inv1));
    }
}

// ---------------------------------------------------------------------------
extern "C" void kernel_launch(void* const* d_in, const int* in_sizes, int n_in,
                              void* d_out, int out_size)
{
    const float* x         = (const float*)d_in[0];
    const int*   start_pos = (const int*)d_in[1];
    const float* cosT      = (const float*)d_in[2];
    const float* sinT      = (const float*)d_in[3];
    const float* wq        = (const float*)d_in[4];
    const float* wk        = (const float*)d_in[5];
    const float* wv        = (const float*)d_in[6];
    const float* wo        = (const float*)d_in[7];
    float* out = (float*)d_out;

    float *q, *k, *v, *attn, *xr, *wqr, *wkr, *wvr, *wor;
    cudaGetSymbolAddress((void**)&q,    g_q);
    cudaGetSymbolAddress((void**)&k,    g_k);
    cudaGetSymbolAddress((void**)&v,    g_v);
    cudaGetSymbolAddress((void**)&attn, g_attn);
    cudaGetSymbolAddress((void**)&xr,   g_xr);
    cudaGetSymbolAddress((void**)&wqr,  g_wqr);
    cudaGetSymbolAddress((void**)&wkr,  g_wkr);
    cudaGetSymbolAddress((void**)&wvr,  g_wvr);
    cudaGetSymbolAddress((void**)&wor,  g_wor);

    // prepass: tf32 rounding (numerics identical to in-GEMM cvt)
    {
        const int big4 = (MROWS * DIM) / 4;           // 4,194,304
        const int sml4 = (DIM * NKV * HD) / 4;        // 1,048,576
        round_tf32_kernel<<<(big4 + 255) / 256, 256>>>(x,  xr,  big4);
        round_tf32_kernel<<<(big4 + 255) / 256, 256>>>(wq, wqr, big4);
        round_tf32_kernel<<<(sml4 + 255) / 256, 256>>>(wk, wkr, sml4);
        round_tf32_kernel<<<(sml4 + 255) / 256, 256>>>(wv, wvr, sml4);
        round_tf32_kernel<<<(big4 + 255) / 256, 256>>>(wo, wor, big4);
    }

    cudaFuncSetAttribute(mma_gemm,    cudaFuncAttributeMaxDynamicSharedMemorySize, GEMM_SMEM);
    cudaFuncSetAttribute(mma_gemm_kv, cudaFuncAttributeMaxDynamicSharedMemorySize, GEMM_SMEM);

    // Q projection + fused K/V projection
    mma_gemm<<<dim3((NH*HD)/256, MROWS/128), 256, GEMM_SMEM>>>(xr, wqr, q, MROWS, NH*HD, DIM);
    mma_gemm_kv<<<dim3(8, MROWS/128), 256, GEMM_SMEM>>>(xr, wkr, wvr, k, v, MROWS, DIM);

    // RoPE
    {
        int totq = BB * SS * NH  * (HD / 2);
        int totk = BB * SS * NKV * (HD / 2);
        rope_kernel<<<(totq + 255) / 256, 256>>>(q, cosT, sinT, start_pos, NH);
        rope_kernel<<<(totk + 255) / 256, 256>>>(k, cosT, sinT, start_pos, NKV);
    }

    // attention (tf32 mma flash)
    cudaFuncSetAttribute(attn_mma, cudaFuncAttributeMaxDynamicSharedMemorySize, ATTN_SMEM);
    attn_mma<<<dim3(SS/128, NH, BB), 256, ATTN_SMEM>>>(q, k, v, attn);

    // output projection (attn already tf32-rounded)
    mma_gemm<<<dim3(DIM/256, MROWS/128), 256, GEMM_SMEM>>>(attn, wor, out, MROWS, DIM, DIM);
}